// round 2
// baseline (speedup 1.0000x reference)
#include <cuda_runtime.h>
#include <cuda_bf16.h>
#include <cstdint>

#define N_USER 100000
#define N_ITEM 200000
#define N_NODE 300000
#define LATDIM 64
#define E_INTER 4000000
#define E_SOC   2000000
#define N_LAYER 4

// Scratch: soc[1..4] (user-only embeddings) and fused[0..4] (full-node embeddings).
// fused[k] first holds inter_lst[k]; the gate kernel overwrites its user rows in
// place with the gated combination, turning it into fused[k].
__device__ float g_soc[4][(size_t)N_USER * LATDIM];
__device__ float g_fused[5][(size_t)N_NODE * LATDIM];

// ---------------------------------------------------------------------------
// zero-fill (float4 vectorized)
// ---------------------------------------------------------------------------
__global__ __launch_bounds__(256) void zero_kernel(float4* __restrict__ p, size_t n4) {
    size_t t = (size_t)blockIdx.x * blockDim.x + threadIdx.x;
    if (t < n4) p[t] = make_float4(0.f, 0.f, 0.f, 0.f);
}

// ---------------------------------------------------------------------------
// SpMM: out[rows[e]] += vals[e] * x[cols[e]]   (64-dim rows)
// 16 lanes per edge, each lane handles 4 consecutive floats (float4 gather +
// one red.global.add.v4.f32 scatter = 1 vector atomic per 16B).
// ---------------------------------------------------------------------------
__global__ __launch_bounds__(256) void spmm_kernel(
    const int* __restrict__ rows, const int* __restrict__ cols,
    const float* __restrict__ vals, const float* __restrict__ x,
    float* __restrict__ out, int nE)
{
    int t = blockIdx.x * blockDim.x + threadIdx.x;
    int e = t >> 4;
    int lane = t & 15;
    if (e >= nE) return;
    int c = __ldg(cols + e);
    int r = __ldg(rows + e);
    float v = __ldg(vals + e);
    float4 xv = __ldg(reinterpret_cast<const float4*>(x + (size_t)c * LATDIM) + lane);
    float* dst = out + (size_t)r * LATDIM + lane * 4;
    asm volatile("red.global.add.v4.f32 [%0], {%1,%2,%3,%4};"
                 :: "l"(dst), "f"(v * xv.x), "f"(v * xv.y), "f"(v * xv.z), "f"(v * xv.w)
                 : "memory");
}

// ---------------------------------------------------------------------------
// Gate: one warp per user row. m = softmax(lrelu([Z,H] @ Wg^T + bg)) over 2;
// F_user_row <- Z*m0 + H*m1  (in place on F).
// ---------------------------------------------------------------------------
__global__ __launch_bounds__(256) void gate_kernel(
    const float* __restrict__ Z,   // soc_k  [N_USER,64]
    float* __restrict__ F,         // fused_k, user rows in/out
    const float* __restrict__ Wg,  // [2,128] for this layer
    const float* __restrict__ bg)  // [2]
{
    int w = (blockIdx.x * blockDim.x + threadIdx.x) >> 5;
    int lane = threadIdx.x & 31;
    if (w >= N_USER) return;
    size_t base = (size_t)w * LATDIM + lane * 2;
    float2 z = *reinterpret_cast<const float2*>(Z + base);
    float2 h = *reinterpret_cast<const float2*>(F + base);
    int d = lane * 2;
    float a0 = z.x * __ldg(Wg + d)       + z.y * __ldg(Wg + d + 1)
             + h.x * __ldg(Wg + 64 + d)  + h.y * __ldg(Wg + 64 + d + 1);
    float a1 = z.x * __ldg(Wg + 128 + d) + z.y * __ldg(Wg + 128 + d + 1)
             + h.x * __ldg(Wg + 192 + d) + h.y * __ldg(Wg + 192 + d + 1);
    #pragma unroll
    for (int o = 16; o; o >>= 1) {
        a0 += __shfl_xor_sync(0xffffffffu, a0, o);
        a1 += __shfl_xor_sync(0xffffffffu, a1, o);
    }
    a0 += __ldg(bg);
    a1 += __ldg(bg + 1);
    a0 = a0 > 0.f ? a0 : 0.01f * a0;
    a1 = a1 > 0.f ? a1 : 0.01f * a1;
    float mx = fmaxf(a0, a1);
    float e0 = __expf(a0 - mx), e1 = __expf(a1 - mx);
    float inv = 1.f / (e0 + e1);
    float m0 = e0 * inv, m1 = e1 * inv;
    float2 o2;
    o2.x = z.x * m0 + h.x * m1;
    o2.y = z.y * m0 + h.y * m1;
    *reinterpret_cast<float2*>(F + base) = o2;
}

// ---------------------------------------------------------------------------
// Final combine: one warp per node. w = softmax(lrelu(concat_k fused[k][n] @ WL^T + b))
// over 5; out[n] = sum_k w_k * fused[k][n].
// ---------------------------------------------------------------------------
__global__ __launch_bounds__(256) void final_kernel(
    const float* __restrict__ F0, const float* __restrict__ F1,
    const float* __restrict__ F2, const float* __restrict__ F3,
    const float* __restrict__ F4,
    const float* __restrict__ WL1, const float* __restrict__ bL1,
    const float* __restrict__ WL2, const float* __restrict__ bL2,
    float* __restrict__ out)
{
    int w = (blockIdx.x * blockDim.x + threadIdx.x) >> 5;
    int lane = threadIdx.x & 31;
    if (w >= N_NODE) return;
    bool isU = (w < N_USER);
    const float* W = isU ? WL1 : WL2;
    const float* b = isU ? bL1 : bL2;
    size_t base = (size_t)w * LATDIM + lane * 2;
    float2 f[5];
    f[0] = *reinterpret_cast<const float2*>(F0 + base);
    f[1] = *reinterpret_cast<const float2*>(F1 + base);
    f[2] = *reinterpret_cast<const float2*>(F2 + base);
    f[3] = *reinterpret_cast<const float2*>(F3 + base);
    f[4] = *reinterpret_cast<const float2*>(F4 + base);
    float lg[5];
    int d = lane * 2;
    #pragma unroll
    for (int j = 0; j < 5; j++) {
        float acc = 0.f;
        #pragma unroll
        for (int k = 0; k < 5; k++) {
            const float* wr = W + j * 320 + k * 64 + d;
            acc += f[k].x * __ldg(wr) + f[k].y * __ldg(wr + 1);
        }
        lg[j] = acc;
    }
    #pragma unroll
    for (int o = 16; o; o >>= 1) {
        #pragma unroll
        for (int j = 0; j < 5; j++) lg[j] += __shfl_xor_sync(0xffffffffu, lg[j], o);
    }
    float mx = -1e30f;
    #pragma unroll
    for (int j = 0; j < 5; j++) {
        lg[j] += __ldg(b + j);
        lg[j] = lg[j] > 0.f ? lg[j] : 0.01f * lg[j];
        mx = fmaxf(mx, lg[j]);
    }
    float s = 0.f;
    #pragma unroll
    for (int j = 0; j < 5; j++) { lg[j] = __expf(lg[j] - mx); s += lg[j]; }
    float inv = 1.f / s;
    float2 o2 = make_float2(0.f, 0.f);
    #pragma unroll
    for (int j = 0; j < 5; j++) {
        float wk = lg[j] * inv;
        o2.x += wk * f[j].x;
        o2.y += wk * f[j].y;
    }
    *reinterpret_cast<float2*>(out + base) = o2;
}

// ---------------------------------------------------------------------------
// host
// ---------------------------------------------------------------------------
static inline int cdiv_ll(long long a, int b) { return (int)((a + b - 1) / b); }

extern "C" void kernel_launch(void* const* d_in, const int* in_sizes, int n_in,
                              void* d_out, int out_size)
{
    const float* uE  = (const float*)d_in[0];
    const float* iE  = (const float*)d_in[1];
    const float* Wg  = (const float*)d_in[2];   // (5,2,128)
    const float* bg  = (const float*)d_in[3];   // (5,2)
    const float* WL1 = (const float*)d_in[4];   // (5,320)
    const float* bL1 = (const float*)d_in[5];
    const float* WL2 = (const float*)d_in[6];
    const float* bL2 = (const float*)d_in[7];
    const int*   ir  = (const int*)d_in[8];
    const int*   ic  = (const int*)d_in[9];
    const float* iv  = (const float*)d_in[10];
    const int*   sr  = (const int*)d_in[11];
    const int*   sc  = (const int*)d_in[12];
    const float* sv  = (const float*)d_in[13];
    float* out = (float*)d_out;

    void* ps; void* pf;
    cudaGetSymbolAddress(&ps, g_soc);
    cudaGetSymbolAddress(&pf, g_fused);

    const size_t nU = (size_t)N_USER * LATDIM;   // 6.4M floats
    const size_t nN = (size_t)N_NODE * LATDIM;   // 19.2M floats

    float* soc[5];
    soc[0] = const_cast<float*>(uE);
    for (int l = 0; l < 4; l++) soc[l + 1] = (float*)ps + (size_t)l * nU;
    float* fused[5];
    for (int k = 0; k < 5; k++) fused[k] = (float*)pf + (size_t)k * nN;

    // fused[0] = ini = concat(uEmbeds, iEmbeds)
    cudaMemcpyAsync(fused[0], uE, nU * sizeof(float), cudaMemcpyDeviceToDevice);
    cudaMemcpyAsync(fused[0] + nU, iE, (size_t)N_ITEM * LATDIM * sizeof(float),
                    cudaMemcpyDeviceToDevice);

    // soc propagation chain: soc[l] = S @ soc[l-1]
    for (int l = 1; l <= N_LAYER; l++) {
        zero_kernel<<<cdiv_ll((long long)nU / 4, 256), 256>>>((float4*)soc[l], nU / 4);
        spmm_kernel<<<cdiv_ll((long long)E_SOC * 16, 256), 256>>>(
            sr, sc, sv, soc[l - 1], soc[l], E_SOC);
    }

    // layer loop: gate user rows of fused[k] in place, then inter SpMM -> fused[k+1]
    for (int k = 0; k <= N_LAYER; k++) {
        gate_kernel<<<cdiv_ll((long long)N_USER * 32, 256), 256>>>(
            soc[k], fused[k], Wg + (size_t)k * 256, bg + (size_t)k * 2);
        if (k < N_LAYER) {  // inter_lst[5] is never consumed -> skip last SpMM
            zero_kernel<<<cdiv_ll((long long)nN / 4, 256), 256>>>((float4*)fused[k + 1], nN / 4);
            spmm_kernel<<<cdiv_ll((long long)E_INTER * 16, 256), 256>>>(
                ir, ic, iv, fused[k], fused[k + 1], E_INTER);
        }
    }

    // final attention combine
    final_kernel<<<cdiv_ll((long long)N_NODE * 32, 256), 256>>>(
        fused[0], fused[1], fused[2], fused[3], fused[4],
        WL1, bL1, WL2, bL2, out);
}

// round 3
// speedup vs baseline: 1.1233x; 1.1233x over previous
#include <cuda_runtime.h>
#include <cuda_bf16.h>
#include <cstdint>

#define N_USER 100000
#define N_ITEM 200000
#define N_NODE 300000
#define LATDIM 64
#define E_INTER 4000000
#define E_SOC   2000000
#define N_LAYER 4

// Scratch: soc[1..4] (user-only), fused[0..4] (full-node), packed edge lists.
__device__ float g_soc[4][(size_t)N_USER * LATDIM];
__device__ float g_fused[5][(size_t)N_NODE * LATDIM];
__device__ float4 g_einter[E_INTER];   // {as_float(col), as_float(row), val, 0}
__device__ float4 g_esoc[E_SOC];

// ---------------------------------------------------------------------------
// pack edge metadata into one 16B record per edge
// ---------------------------------------------------------------------------
__global__ __launch_bounds__(256) void pack_kernel(
    float4* __restrict__ out, const int* __restrict__ rows,
    const int* __restrict__ cols, const float* __restrict__ vals, int n)
{
    int e = blockIdx.x * blockDim.x + threadIdx.x;
    if (e >= n) return;
    float4 p;
    p.x = __int_as_float(__ldg(cols + e));
    p.y = __int_as_float(__ldg(rows + e));
    p.z = __ldg(vals + e);
    p.w = 0.f;
    out[e] = p;
}

// ---------------------------------------------------------------------------
// Dual SpMM: blocks [0, blocksA) process edge set A, the rest process B.
// 16 lanes per edge-group; each group handles edges g and g+nH (2-way ILP:
// both gathers in flight before the REDs). One broadcast LDG.128 per edge for
// metadata, float4 gather, red.global.add.v4.f32 scatter.
// ---------------------------------------------------------------------------
__device__ __forceinline__ void red4(float* dst, float v, float4 x) {
    asm volatile("red.global.add.v4.f32 [%0], {%1,%2,%3,%4};"
                 :: "l"(dst), "f"(v * x.x), "f"(v * x.y), "f"(v * x.z), "f"(v * x.w)
                 : "memory");
}

__global__ __launch_bounds__(256) void spmm_dual_kernel(
    const float4* __restrict__ eA, const float* __restrict__ xA,
    float* __restrict__ oA, int nA,
    const float4* __restrict__ eB, const float* __restrict__ xB,
    float* __restrict__ oB, int nB,
    int blocksA)
{
    const float4* E; const float* X; float* O; int n; unsigned b;
    if (blockIdx.x < (unsigned)blocksA) { E = eA; X = xA; O = oA; n = nA; b = blockIdx.x; }
    else                                { E = eB; X = xB; O = oB; n = nB; b = blockIdx.x - blocksA; }

    int t = (int)b * 256 + (int)threadIdx.x;
    int lane = t & 15;
    int g = t >> 4;
    int nH = (n + 1) >> 1;
    if (g >= nH) return;

    float4 m0 = __ldg(E + g);
    int e1 = g + nH;
    bool h1 = (e1 < n);
    float4 m1 = __ldg(E + (h1 ? e1 : g));

    int c0 = __float_as_int(m0.x), r0 = __float_as_int(m0.y);
    int c1 = __float_as_int(m1.x), r1 = __float_as_int(m1.y);

    float4 x0 = __ldg(reinterpret_cast<const float4*>(X + (size_t)c0 * LATDIM) + lane);
    float4 x1 = __ldg(reinterpret_cast<const float4*>(X + (size_t)c1 * LATDIM) + lane);

    red4(O + (size_t)r0 * LATDIM + lane * 4, m0.z, x0);
    if (h1) red4(O + (size_t)r1 * LATDIM + lane * 4, m1.z, x1);
}

// ---------------------------------------------------------------------------
// Gate: one warp per user row. m = softmax(lrelu([Z,H] @ Wg^T + bg)) over 2;
// F_user_row <- Z*m0 + H*m1  (in place on F).
// ---------------------------------------------------------------------------
__global__ __launch_bounds__(256) void gate_kernel(
    const float* __restrict__ Z,   // soc_k  [N_USER,64]
    float* __restrict__ F,         // fused_k, user rows in/out
    const float* __restrict__ Wg,  // [2,128] for this layer
    const float* __restrict__ bg)  // [2]
{
    int w = (blockIdx.x * blockDim.x + threadIdx.x) >> 5;
    int lane = threadIdx.x & 31;
    if (w >= N_USER) return;
    size_t base = (size_t)w * LATDIM + lane * 2;
    float2 z = *reinterpret_cast<const float2*>(Z + base);
    float2 h = *reinterpret_cast<const float2*>(F + base);
    int d = lane * 2;
    float a0 = z.x * __ldg(Wg + d)       + z.y * __ldg(Wg + d + 1)
             + h.x * __ldg(Wg + 64 + d)  + h.y * __ldg(Wg + 64 + d + 1);
    float a1 = z.x * __ldg(Wg + 128 + d) + z.y * __ldg(Wg + 128 + d + 1)
             + h.x * __ldg(Wg + 192 + d) + h.y * __ldg(Wg + 192 + d + 1);
    #pragma unroll
    for (int o = 16; o; o >>= 1) {
        a0 += __shfl_xor_sync(0xffffffffu, a0, o);
        a1 += __shfl_xor_sync(0xffffffffu, a1, o);
    }
    a0 += __ldg(bg);
    a1 += __ldg(bg + 1);
    a0 = a0 > 0.f ? a0 : 0.01f * a0;
    a1 = a1 > 0.f ? a1 : 0.01f * a1;
    float mx = fmaxf(a0, a1);
    float e0 = __expf(a0 - mx), e1 = __expf(a1 - mx);
    float inv = 1.f / (e0 + e1);
    float m0 = e0 * inv, m1 = e1 * inv;
    float2 o2;
    o2.x = z.x * m0 + h.x * m1;
    o2.y = z.y * m0 + h.y * m1;
    *reinterpret_cast<float2*>(F + base) = o2;
}

// ---------------------------------------------------------------------------
// Final combine: one warp per node. w = softmax(lrelu(concat_k fused[k][n] @ WL^T + b))
// over 5; out[n] = sum_k w_k * fused[k][n].
// ---------------------------------------------------------------------------
__global__ __launch_bounds__(256) void final_kernel(
    const float* __restrict__ F0, const float* __restrict__ F1,
    const float* __restrict__ F2, const float* __restrict__ F3,
    const float* __restrict__ F4,
    const float* __restrict__ WL1, const float* __restrict__ bL1,
    const float* __restrict__ WL2, const float* __restrict__ bL2,
    float* __restrict__ out)
{
    int w = (blockIdx.x * blockDim.x + threadIdx.x) >> 5;
    int lane = threadIdx.x & 31;
    if (w >= N_NODE) return;
    bool isU = (w < N_USER);
    const float* W = isU ? WL1 : WL2;
    const float* b = isU ? bL1 : bL2;
    size_t base = (size_t)w * LATDIM + lane * 2;
    float2 f[5];
    f[0] = *reinterpret_cast<const float2*>(F0 + base);
    f[1] = *reinterpret_cast<const float2*>(F1 + base);
    f[2] = *reinterpret_cast<const float2*>(F2 + base);
    f[3] = *reinterpret_cast<const float2*>(F3 + base);
    f[4] = *reinterpret_cast<const float2*>(F4 + base);
    float lg[5];
    int d = lane * 2;
    #pragma unroll
    for (int j = 0; j < 5; j++) {
        float acc = 0.f;
        #pragma unroll
        for (int k = 0; k < 5; k++) {
            const float* wr = W + j * 320 + k * 64 + d;
            acc += f[k].x * __ldg(wr) + f[k].y * __ldg(wr + 1);
        }
        lg[j] = acc;
    }
    #pragma unroll
    for (int o = 16; o; o >>= 1) {
        #pragma unroll
        for (int j = 0; j < 5; j++) lg[j] += __shfl_xor_sync(0xffffffffu, lg[j], o);
    }
    float mx = -1e30f;
    #pragma unroll
    for (int j = 0; j < 5; j++) {
        lg[j] += __ldg(b + j);
        lg[j] = lg[j] > 0.f ? lg[j] : 0.01f * lg[j];
        mx = fmaxf(mx, lg[j]);
    }
    float s = 0.f;
    #pragma unroll
    for (int j = 0; j < 5; j++) { lg[j] = __expf(lg[j] - mx); s += lg[j]; }
    float inv = 1.f / s;
    float2 o2 = make_float2(0.f, 0.f);
    #pragma unroll
    for (int j = 0; j < 5; j++) {
        float wk = lg[j] * inv;
        o2.x += wk * f[j].x;
        o2.y += wk * f[j].y;
    }
    *reinterpret_cast<float2*>(out + base) = o2;
}

// ---------------------------------------------------------------------------
// host
// ---------------------------------------------------------------------------
static inline int cdiv_ll(long long a, int b) { return (int)((a + b - 1) / b); }

extern "C" void kernel_launch(void* const* d_in, const int* in_sizes, int n_in,
                              void* d_out, int out_size)
{
    const float* uE  = (const float*)d_in[0];
    const float* iE  = (const float*)d_in[1];
    const float* Wg  = (const float*)d_in[2];   // (5,2,128)
    const float* bg  = (const float*)d_in[3];   // (5,2)
    const float* WL1 = (const float*)d_in[4];   // (5,320)
    const float* bL1 = (const float*)d_in[5];
    const float* WL2 = (const float*)d_in[6];
    const float* bL2 = (const float*)d_in[7];
    const int*   ir  = (const int*)d_in[8];
    const int*   ic  = (const int*)d_in[9];
    const float* iv  = (const float*)d_in[10];
    const int*   sr  = (const int*)d_in[11];
    const int*   sc  = (const int*)d_in[12];
    const float* sv  = (const float*)d_in[13];
    float* out = (float*)d_out;

    void *ps, *pf, *pei, *pes;
    cudaGetSymbolAddress(&ps, g_soc);
    cudaGetSymbolAddress(&pf, g_fused);
    cudaGetSymbolAddress(&pei, g_einter);
    cudaGetSymbolAddress(&pes, g_esoc);

    const size_t nU = (size_t)N_USER * LATDIM;   // 6.4M floats
    const size_t nN = (size_t)N_NODE * LATDIM;   // 19.2M floats

    float* soc[5];
    soc[0] = const_cast<float*>(uE);
    for (int l = 0; l < 4; l++) soc[l + 1] = (float*)ps + (size_t)l * nU;
    float* fused[5];
    for (int k = 0; k < 5; k++) fused[k] = (float*)pf + (size_t)k * nN;
    float4* eI = (float4*)pei;
    float4* eS = (float4*)pes;

    // Zero all accumulation targets upfront (soc[1..4], fused[1..4]).
    cudaMemsetAsync(ps, 0, 4 * nU * sizeof(float));
    cudaMemsetAsync((float*)pf + nN, 0, 4 * nN * sizeof(float));

    // Pack edge metadata: one 16B record per edge.
    pack_kernel<<<cdiv_ll(E_INTER, 256), 256>>>(eI, ir, ic, iv, E_INTER);
    pack_kernel<<<cdiv_ll(E_SOC, 256), 256>>>(eS, sr, sc, sv, E_SOC);

    // fused[0] = ini = concat(uEmbeds, iEmbeds). gate0 is an exact identity
    // (Z == H == uE and m0+m1 == 1), so fused[0] stays ini.
    cudaMemcpyAsync(fused[0], uE, nU * sizeof(float), cudaMemcpyDeviceToDevice);
    cudaMemcpyAsync(fused[0] + nU, iE, (size_t)N_ITEM * LATDIM * sizeof(float),
                    cudaMemcpyDeviceToDevice);

    // Grid geometry for the dual SpMM (16 lanes per 2-edge group).
    const int nHI = (E_INTER + 1) / 2;            // 2M groups
    const int nHS = (E_SOC + 1) / 2;              // 1M groups
    const int blocksA = cdiv_ll((long long)nHI * 16, 256);   // inter part
    const int blocksB = cdiv_ll((long long)nHS * 16, 256);   // soc part
    const int blocksTot = blocksA + blocksB;

    // Paired layers: (inter_k || soc_{k+1}) then gate_{k+1}.
    //   inter_k reads gated fused[k] -> fused[k+1]
    //   soc_{k+1} reads soc[k]       -> soc[k+1]
    for (int k = 0; k < N_LAYER; k++) {
        spmm_dual_kernel<<<blocksTot, 256>>>(
            eI, fused[k], fused[k + 1], E_INTER,
            eS, soc[k], soc[k + 1], E_SOC,
            blocksA);
        gate_kernel<<<cdiv_ll((long long)N_USER * 32, 256), 256>>>(
            soc[k + 1], fused[k + 1],
            Wg + (size_t)(k + 1) * 256, bg + (size_t)(k + 1) * 2);
    }

    // final attention combine
    final_kernel<<<cdiv_ll((long long)N_NODE * 32, 256), 256>>>(
        fused[0], fused[1], fused[2], fused[3], fused[4],
        WL1, bL1, WL2, bL2, out);
}

// round 6
// speedup vs baseline: 1.2863x; 1.1451x over previous
#include <cuda_runtime.h>
#include <cuda_bf16.h>
#include <cstdint>

#define N_USER 100000
#define N_ITEM 200000
#define N_NODE 300000
#define LATDIM 64
#define E_INTER 4000000
#define E_SOC   2000000
#define N_LAYER 4

// Scratch: soc[1..4] (user-only), fused[0..4] (full-node), packed edge lists.
__device__ float g_soc[4][(size_t)N_USER * LATDIM];
__device__ float g_fused[5][(size_t)N_NODE * LATDIM];
__device__ float4 g_einter[E_INTER];   // {as_float(col), as_float(row), val, 0}
__device__ float4 g_esoc[E_SOC];

// ---------------------------------------------------------------------------
// Preamble: one kernel packs both edge lists, builds fused[0] = concat(uE,iE),
// and zeroes the layer-1 accumulation targets (fused[1], soc[1]).
// ---------------------------------------------------------------------------
#define PB_I 15625           // E_INTER / 256
#define PB_S 7813            // ceil(E_SOC / 256)
#define PB_C 4096            // grid-stride copy of fused[0]
#define PB_Z 2048            // grid-stride zero of fused[1], soc[1]

__global__ __launch_bounds__(256) void preamble_kernel(
    float4* __restrict__ eI, const int* __restrict__ ir,
    const int* __restrict__ ic, const float* __restrict__ iv,
    float4* __restrict__ eS, const int* __restrict__ sr,
    const int* __restrict__ sc, const float* __restrict__ sv,
    const float4* __restrict__ uE4, const float4* __restrict__ iE4,
    float4* __restrict__ f0,
    float4* __restrict__ zA, size_t nzA,   // fused[1] as float4
    float4* __restrict__ zB, size_t nzB)   // soc[1]   as float4
{
    unsigned b = blockIdx.x;
    int tid = threadIdx.x;
    if (b < PB_I) {
        int e = (int)b * 256 + tid;
        float4 p;
        p.x = __int_as_float(__ldg(ic + e));
        p.y = __int_as_float(__ldg(ir + e));
        p.z = __ldg(iv + e);
        p.w = 0.f;
        eI[e] = p;
    } else if (b < PB_I + PB_S) {
        int e = (int)(b - PB_I) * 256 + tid;
        if (e < E_SOC) {
            float4 p;
            p.x = __int_as_float(__ldg(sc + e));
            p.y = __int_as_float(__ldg(sr + e));
            p.z = __ldg(sv + e);
            p.w = 0.f;
            eS[e] = p;
        }
    } else if (b < PB_I + PB_S + PB_C) {
        const size_t nU4 = (size_t)N_USER * LATDIM / 4;
        const size_t nN4 = (size_t)N_NODE * LATDIM / 4;
        size_t stride = (size_t)PB_C * 256;
        for (size_t i = (size_t)(b - PB_I - PB_S) * 256 + tid; i < nN4; i += stride)
            f0[i] = (i < nU4) ? __ldg(uE4 + i) : __ldg(iE4 + (i - nU4));
    } else {
        size_t stride = (size_t)PB_Z * 256;
        float4 z = make_float4(0.f, 0.f, 0.f, 0.f);
        size_t tot = nzA + nzB;
        for (size_t i = (size_t)(b - PB_I - PB_S - PB_C) * 256 + tid; i < tot; i += stride) {
            if (i < nzA) zA[i] = z; else zB[i - nzA] = z;
        }
    }
}

// ---------------------------------------------------------------------------
// Dual SpMM with 4-way edge ILP. Blocks [0, blocksA) = edge set A (inter),
// rest = set B (soc). 16 lanes per group; group g handles edge pairs
// {2g, 2g+1} and {2g+nH, 2g+nH+1} via two 32B ld.global.nc.L2::evict_first
// loads (the only legal evict_first vector form on sm_103). Gathers are
// float4 __ldg; scatter is red.global.add.v4.f32.
// ---------------------------------------------------------------------------
struct EdgePair { float4 a, b; };

__device__ __forceinline__ EdgePair ldg_pair_ef(const float4* p) {
    EdgePair r;
    asm volatile("ld.global.nc.L2::evict_first.v4.b64 {%0,%1,%2,%3}, [%4];"
                 : "=l"(*reinterpret_cast<uint64_t*>(&r.a.x)),
                   "=l"(*reinterpret_cast<uint64_t*>(&r.a.z)),
                   "=l"(*reinterpret_cast<uint64_t*>(&r.b.x)),
                   "=l"(*reinterpret_cast<uint64_t*>(&r.b.z))
                 : "l"(p));
    return r;
}

__device__ __forceinline__ void red4(float* dst, float v, float4 x) {
    asm volatile("red.global.add.v4.f32 [%0], {%1,%2,%3,%4};"
                 :: "l"(dst), "f"(v * x.x), "f"(v * x.y), "f"(v * x.z), "f"(v * x.w)
                 : "memory");
}

__global__ __launch_bounds__(256) void spmm_dual_kernel(
    const float4* __restrict__ eA, const float* __restrict__ xA,
    float* __restrict__ oA, int nA,
    const float4* __restrict__ eB, const float* __restrict__ xB,
    float* __restrict__ oB, int nB,
    int blocksA)
{
    const float4* E; const float* X; float* O; int n; unsigned b;
    if (blockIdx.x < (unsigned)blocksA) { E = eA; X = xA; O = oA; n = nA; b = blockIdx.x; }
    else                                { E = eB; X = xB; O = oB; n = nB; b = blockIdx.x - blocksA; }

    int t = (int)b * 256 + (int)threadIdx.x;
    int lane = t & 15;
    int g = t >> 4;
    int nH = n >> 1;                 // both edge counts are even
    int nQ = n >> 2;
    if (g >= nQ) return;

    EdgePair p0 = ldg_pair_ef(E + 2 * g);        // edges 2g, 2g+1
    EdgePair p1 = ldg_pair_ef(E + 2 * g + nH);   // edges 2g+nH, 2g+nH+1

    int c0 = __float_as_int(p0.a.x), r0 = __float_as_int(p0.a.y);
    int c1 = __float_as_int(p0.b.x), r1 = __float_as_int(p0.b.y);
    int c2 = __float_as_int(p1.a.x), r2 = __float_as_int(p1.a.y);
    int c3 = __float_as_int(p1.b.x), r3 = __float_as_int(p1.b.y);

    float4 x0 = __ldg(reinterpret_cast<const float4*>(X + (size_t)c0 * LATDIM) + lane);
    float4 x1 = __ldg(reinterpret_cast<const float4*>(X + (size_t)c1 * LATDIM) + lane);
    float4 x2 = __ldg(reinterpret_cast<const float4*>(X + (size_t)c2 * LATDIM) + lane);
    float4 x3 = __ldg(reinterpret_cast<const float4*>(X + (size_t)c3 * LATDIM) + lane);

    red4(O + (size_t)r0 * LATDIM + lane * 4, p0.a.z, x0);
    red4(O + (size_t)r1 * LATDIM + lane * 4, p0.b.z, x1);
    red4(O + (size_t)r2 * LATDIM + lane * 4, p1.a.z, x2);
    red4(O + (size_t)r3 * LATDIM + lane * 4, p1.b.z, x3);
}

// ---------------------------------------------------------------------------
// Gate: one warp per user row (blocks [0, GATE_B)); blocks [GATE_B, GATE_B+GATE_Z)
// zero the NEXT layer's accumulation targets (overlapped with gate latency).
// ---------------------------------------------------------------------------
#define GATE_B 12500         // N_USER * 32 / 256
#define GATE_Z 2048

__global__ __launch_bounds__(256) void gate_kernel(
    const float* __restrict__ Z,   // soc_k  [N_USER,64]
    float* __restrict__ F,         // fused_k, user rows in/out
    const float* __restrict__ Wg,  // [2,128] for this layer
    const float* __restrict__ bg,  // [2]
    float4* __restrict__ zA, size_t nzA,   // next fused buffer (or 0)
    float4* __restrict__ zB, size_t nzB)   // next soc buffer (or 0)
{
    if (blockIdx.x >= GATE_B) {
        size_t stride = (size_t)GATE_Z * 256;
        float4 z = make_float4(0.f, 0.f, 0.f, 0.f);
        size_t tot = nzA + nzB;
        for (size_t i = (size_t)(blockIdx.x - GATE_B) * 256 + threadIdx.x; i < tot; i += stride) {
            if (i < nzA) zA[i] = z; else zB[i - nzA] = z;
        }
        return;
    }
    int w = (blockIdx.x * blockDim.x + threadIdx.x) >> 5;
    int lane = threadIdx.x & 31;
    size_t base = (size_t)w * LATDIM + lane * 2;
    float2 z = *reinterpret_cast<const float2*>(Z + base);
    float2 h = *reinterpret_cast<const float2*>(F + base);
    int d = lane * 2;
    float a0 = z.x * __ldg(Wg + d)       + z.y * __ldg(Wg + d + 1)
             + h.x * __ldg(Wg + 64 + d)  + h.y * __ldg(Wg + 64 + d + 1);
    float a1 = z.x * __ldg(Wg + 128 + d) + z.y * __ldg(Wg + 128 + d + 1)
             + h.x * __ldg(Wg + 192 + d) + h.y * __ldg(Wg + 192 + d + 1);
    #pragma unroll
    for (int o = 16; o; o >>= 1) {
        a0 += __shfl_xor_sync(0xffffffffu, a0, o);
        a1 += __shfl_xor_sync(0xffffffffu, a1, o);
    }
    a0 += __ldg(bg);
    a1 += __ldg(bg + 1);
    a0 = a0 > 0.f ? a0 : 0.01f * a0;
    a1 = a1 > 0.f ? a1 : 0.01f * a1;
    float mx = fmaxf(a0, a1);
    float e0 = __expf(a0 - mx), e1 = __expf(a1 - mx);
    float inv = 1.f / (e0 + e1);
    float m0 = e0 * inv, m1 = e1 * inv;
    float2 o2;
    o2.x = z.x * m0 + h.x * m1;
    o2.y = z.y * m0 + h.y * m1;
    *reinterpret_cast<float2*>(F + base) = o2;
}

// ---------------------------------------------------------------------------
// Final combine: one warp per node.
// ---------------------------------------------------------------------------
__global__ __launch_bounds__(256) void final_kernel(
    const float* __restrict__ F0, const float* __restrict__ F1,
    const float* __restrict__ F2, const float* __restrict__ F3,
    const float* __restrict__ F4,
    const float* __restrict__ WL1, const float* __restrict__ bL1,
    const float* __restrict__ WL2, const float* __restrict__ bL2,
    float* __restrict__ out)
{
    int w = (blockIdx.x * blockDim.x + threadIdx.x) >> 5;
    int lane = threadIdx.x & 31;
    if (w >= N_NODE) return;
    bool isU = (w < N_USER);
    const float* W = isU ? WL1 : WL2;
    const float* b = isU ? bL1 : bL2;
    size_t base = (size_t)w * LATDIM + lane * 2;
    float2 f[5];
    f[0] = *reinterpret_cast<const float2*>(F0 + base);
    f[1] = *reinterpret_cast<const float2*>(F1 + base);
    f[2] = *reinterpret_cast<const float2*>(F2 + base);
    f[3] = *reinterpret_cast<const float2*>(F3 + base);
    f[4] = *reinterpret_cast<const float2*>(F4 + base);
    float lg[5];
    int d = lane * 2;
    #pragma unroll
    for (int j = 0; j < 5; j++) {
        float acc = 0.f;
        #pragma unroll
        for (int k = 0; k < 5; k++) {
            const float* wr = W + j * 320 + k * 64 + d;
            acc += f[k].x * __ldg(wr) + f[k].y * __ldg(wr + 1);
        }
        lg[j] = acc;
    }
    #pragma unroll
    for (int o = 16; o; o >>= 1) {
        #pragma unroll
        for (int j = 0; j < 5; j++) lg[j] += __shfl_xor_sync(0xffffffffu, lg[j], o);
    }
    float mx = -1e30f;
    #pragma unroll
    for (int j = 0; j < 5; j++) {
        lg[j] += __ldg(b + j);
        lg[j] = lg[j] > 0.f ? lg[j] : 0.01f * lg[j];
        mx = fmaxf(mx, lg[j]);
    }
    float s = 0.f;
    #pragma unroll
    for (int j = 0; j < 5; j++) { lg[j] = __expf(lg[j] - mx); s += lg[j]; }
    float inv = 1.f / s;
    float2 o2 = make_float2(0.f, 0.f);
    #pragma unroll
    for (int j = 0; j < 5; j++) {
        float wk = lg[j] * inv;
        o2.x += wk * f[j].x;
        o2.y += wk * f[j].y;
    }
    *reinterpret_cast<float2*>(out + base) = o2;
}

// ---------------------------------------------------------------------------
// host
// ---------------------------------------------------------------------------
static inline int cdiv_ll(long long a, int b) { return (int)((a + b - 1) / b); }

extern "C" void kernel_launch(void* const* d_in, const int* in_sizes, int n_in,
                              void* d_out, int out_size)
{
    const float* uE  = (const float*)d_in[0];
    const float* iE  = (const float*)d_in[1];
    const float* Wg  = (const float*)d_in[2];   // (5,2,128)
    const float* bg  = (const float*)d_in[3];   // (5,2)
    const float* WL1 = (const float*)d_in[4];   // (5,320)
    const float* bL1 = (const float*)d_in[5];
    const float* WL2 = (const float*)d_in[6];
    const float* bL2 = (const float*)d_in[7];
    const int*   ir  = (const int*)d_in[8];
    const int*   ic  = (const int*)d_in[9];
    const float* iv  = (const float*)d_in[10];
    const int*   sr  = (const int*)d_in[11];
    const int*   sc  = (const int*)d_in[12];
    const float* sv  = (const float*)d_in[13];
    float* out = (float*)d_out;

    void *ps, *pf, *pei, *pes;
    cudaGetSymbolAddress(&ps, g_soc);
    cudaGetSymbolAddress(&pf, g_fused);
    cudaGetSymbolAddress(&pei, g_einter);
    cudaGetSymbolAddress(&pes, g_esoc);

    const size_t nU = (size_t)N_USER * LATDIM;   // 6.4M floats
    const size_t nN = (size_t)N_NODE * LATDIM;   // 19.2M floats

    float* soc[5];
    soc[0] = const_cast<float*>(uE);
    for (int l = 0; l < 4; l++) soc[l + 1] = (float*)ps + (size_t)l * nU;
    float* fused[5];
    for (int k = 0; k < 5; k++) fused[k] = (float*)pf + (size_t)k * nN;
    float4* eI = (float4*)pei;
    float4* eS = (float4*)pes;

    // Preamble: pack edges, build fused[0] (gate0 is exact identity), zero
    // layer-1 targets — one full-chip launch.
    preamble_kernel<<<PB_I + PB_S + PB_C + PB_Z, 256>>>(
        eI, ir, ic, iv, eS, sr, sc, sv,
        (const float4*)uE, (const float4*)iE, (float4*)fused[0],
        (float4*)fused[1], nN / 4, (float4*)soc[1], nU / 4);

    // Grid geometry for the dual SpMM (16 lanes per 4-edge group).
    const int blocksA = cdiv_ll((long long)(E_INTER / 4) * 16, 256);  // 62500
    const int blocksB = cdiv_ll((long long)(E_SOC / 4) * 16, 256);    // 31250
    const int blocksTot = blocksA + blocksB;

    // Paired layers: (inter_k || soc_{k+1}) then gate_{k+1} (+ zero of the
    // layer-(k+2) accumulation targets, overlapped with the gate).
    for (int k = 0; k < N_LAYER; k++) {
        spmm_dual_kernel<<<blocksTot, 256>>>(
            eI, fused[k], fused[k + 1], E_INTER,
            eS, soc[k], soc[k + 1], E_SOC,
            blocksA);
        bool more = (k + 2 <= N_LAYER);
        gate_kernel<<<GATE_B + GATE_Z, 256>>>(
            soc[k + 1], fused[k + 1],
            Wg + (size_t)(k + 1) * 256, bg + (size_t)(k + 1) * 2,
            more ? (float4*)fused[k + 2] : (float4*)nullptr, more ? nN / 4 : 0,
            more ? (float4*)soc[k + 2]   : (float4*)nullptr, more ? nU / 4 : 0);
    }

    // final attention combine
    final_kernel<<<cdiv_ll((long long)N_NODE * 32, 256), 256>>>(
        fused[0], fused[1], fused[2], fused[3], fused[4],
        WL1, bL1, WL2, bL2, out);
}

// round 7
// speedup vs baseline: 1.4436x; 1.1223x over previous
#include <cuda_runtime.h>
#include <cuda_fp16.h>
#include <cstdint>

#define N_USER 100000
#define N_ITEM 200000
#define N_NODE 300000
#define LATDIM 64
#define E_INTER 4000000
#define E_SOC   2000000
#define N_LAYER 4

#define NUF ((size_t)N_USER * LATDIM)   // 6.4M floats
#define NNF ((size_t)N_NODE * LATDIM)   // 19.2M floats

// f32 accumulators: soc[1..4], fused[1..4] (fused[0] == concat(uE,iE) is read
// directly from the inputs; gate0 is an exact identity).
__device__ float g_soc[4][NUF];
__device__ float g_fused[4][NNF];
// fp16 gather mirrors: fused16[k] (k=0..3) feed inter SpMM k; soc16[l] (l=1..3)
// feed soc SpMM l+1 (layer-0 soc source aliases fused16[0]'s user rows).
__device__ __half g_fused16[4][NNF];
__device__ __half g_soc16[3][NUF];
// packed edges: col(19b) | row(19b)<<19 | fp16(val)<<48, 8 B each.
__device__ __align__(16) unsigned long long g_epack[E_INTER + E_SOC];

// ---------------------------------------------------------------------------
// Preamble: pack both edge lists, build fused16[0] = fp16(concat(uE,iE)),
// zero layer-1 f32 accumulators.
// ---------------------------------------------------------------------------
#define PB_I 15625           // E_INTER / 256
#define PB_S 7813            // ceil(E_SOC / 256)
#define PB_H 1024            // fp16 build of fused16[0]
#define PB_Z 1024            // zero fused[1], soc[1]

__device__ __forceinline__ unsigned long long pack_edge(int col, int row, float v) {
    unsigned short hb = __half_as_ushort(__float2half_rn(v));
    return (unsigned long long)(unsigned)col
         | ((unsigned long long)(unsigned)row << 19)
         | ((unsigned long long)hb << 48);
}

__global__ __launch_bounds__(256) void preamble_kernel(
    unsigned long long* __restrict__ eI, const int* __restrict__ ir,
    const int* __restrict__ ic, const float* __restrict__ iv,
    unsigned long long* __restrict__ eS, const int* __restrict__ sr,
    const int* __restrict__ sc, const float* __restrict__ sv,
    const float4* __restrict__ uE4, const float4* __restrict__ iE4,
    uint2* __restrict__ h0,                // fused16[0] as 4-half units
    float4* __restrict__ zA, size_t nzA,   // fused[1]
    float4* __restrict__ zB, size_t nzB)   // soc[1]
{
    unsigned b = blockIdx.x;
    int tid = threadIdx.x;
    if (b < PB_I) {
        int e = (int)b * 256 + tid;
        eI[e] = pack_edge(__ldg(ic + e), __ldg(ir + e), __ldg(iv + e));
    } else if (b < PB_I + PB_S) {
        int e = (int)(b - PB_I) * 256 + tid;
        if (e < E_SOC)
            eS[e] = pack_edge(__ldg(sc + e), __ldg(sr + e), __ldg(sv + e));
    } else if (b < PB_I + PB_S + PB_H) {
        const size_t nU4 = NUF / 4, nN4 = NNF / 4;
        size_t stride = (size_t)PB_H * 256;
        for (size_t i = (size_t)(b - PB_I - PB_S) * 256 + tid; i < nN4; i += stride) {
            float4 v = (i < nU4) ? __ldg(uE4 + i) : __ldg(iE4 + (i - nU4));
            __half2 a = __floats2half2_rn(v.x, v.y);
            __half2 c = __floats2half2_rn(v.z, v.w);
            uint2 st;
            st.x = *reinterpret_cast<unsigned*>(&a);
            st.y = *reinterpret_cast<unsigned*>(&c);
            h0[i] = st;
        }
    } else {
        size_t stride = (size_t)PB_Z * 256;
        float4 z = make_float4(0.f, 0.f, 0.f, 0.f);
        size_t tot = nzA + nzB;
        for (size_t i = (size_t)(b - PB_I - PB_S - PB_H) * 256 + tid; i < tot; i += stride) {
            if (i < nzA) zA[i] = z; else zB[i - nzA] = z;
        }
    }
}

// ---------------------------------------------------------------------------
// Dual SpMM, fp16 gather / f32 RED scatter, 4 edges per thread.
// 16 lanes per group; one LDG.128 fetches 2 packed edge records. Group g
// handles records {2g,2g+1} and {2(g+nQ), 2(g+nQ)+1}.
// ---------------------------------------------------------------------------
__device__ __forceinline__ void red4(float* dst, float v, float4 x) {
    asm volatile("red.global.add.v4.f32 [%0], {%1,%2,%3,%4};"
                 :: "l"(dst), "f"(v * x.x), "f"(v * x.y), "f"(v * x.z), "f"(v * x.w)
                 : "memory");
}

__device__ __forceinline__ void unpack_edge(unsigned lo, unsigned hi,
                                            int& col, int& row, float& val) {
    col = (int)(lo & 0x7FFFFu);
    row = (int)(((lo >> 19) | (hi << 13)) & 0x7FFFFu);
    val = __half2float(__ushort_as_half((unsigned short)(hi >> 16)));
}

__device__ __forceinline__ float4 gather16(const __half* X16, int row, int lane) {
    uint2 h = __ldg(reinterpret_cast<const uint2*>(X16 + (size_t)row * LATDIM) + lane);
    __half2 a = *reinterpret_cast<__half2*>(&h.x);
    __half2 b = *reinterpret_cast<__half2*>(&h.y);
    float2 fa = __half22float2(a), fb = __half22float2(b);
    return make_float4(fa.x, fa.y, fb.x, fb.y);
}

__global__ __launch_bounds__(256) void spmm_dual_kernel(
    const unsigned long long* __restrict__ eA, const __half* __restrict__ xA,
    float* __restrict__ oA, int nA,
    const unsigned long long* __restrict__ eB, const __half* __restrict__ xB,
    float* __restrict__ oB, int nB,
    int blocksA)
{
    const unsigned long long* E; const __half* X; float* O; int n; unsigned b;
    if (blockIdx.x < (unsigned)blocksA) { E = eA; X = xA; O = oA; n = nA; b = blockIdx.x; }
    else                                { E = eB; X = xB; O = oB; n = nB; b = blockIdx.x - blocksA; }

    int t = (int)b * 256 + (int)threadIdx.x;
    int lane = t & 15;
    int g = t >> 4;
    int nQ = n >> 2;                 // groups; also pair-stride
    if (g >= nQ) return;

    const uint4* P = reinterpret_cast<const uint4*>(E);
    uint4 q0 = __ldg(P + g);         // records 2g, 2g+1
    uint4 q1 = __ldg(P + g + nQ);    // records 2(g+nQ), 2(g+nQ)+1

    int c0, r0, c1, r1, c2, r2, c3, r3;
    float v0, v1, v2, v3;
    unpack_edge(q0.x, q0.y, c0, r0, v0);
    unpack_edge(q0.z, q0.w, c1, r1, v1);
    unpack_edge(q1.x, q1.y, c2, r2, v2);
    unpack_edge(q1.z, q1.w, c3, r3, v3);

    float4 x0 = gather16(X, c0, lane);
    float4 x1 = gather16(X, c1, lane);
    float4 x2 = gather16(X, c2, lane);
    float4 x3 = gather16(X, c3, lane);

    red4(O + (size_t)r0 * LATDIM + lane * 4, v0, x0);
    red4(O + (size_t)r1 * LATDIM + lane * 4, v1, x1);
    red4(O + (size_t)r2 * LATDIM + lane * 4, v2, x2);
    red4(O + (size_t)r3 * LATDIM + lane * 4, v3, x3);
}

// ---------------------------------------------------------------------------
// Gate: blocks [0,GATE_B): one warp per user row — gate in place on F, and
// (when emitting) write fp16 mirrors of Z (soc16 next) and gated row (fused16).
// Blocks [GATE_B, ..): convert item rows of F -> fused16, zero next-layer
// f32 accumulators.
// ---------------------------------------------------------------------------
#define GATE_B 12500         // N_USER * 32 / 256
#define GATE_X 2048

__global__ __launch_bounds__(256) void gate_kernel(
    const float* __restrict__ Z,    // soc_k [N_USER,64]
    float* __restrict__ F,          // fused_k, user rows in/out
    const float* __restrict__ Wg, const float* __restrict__ bg,
    __half* __restrict__ Z16,       // soc16 mirror of Z (or null)
    __half* __restrict__ F16,       // fused16 mirror, user rows (or null)
    const float4* __restrict__ cvtSrc,  // F item rows as float4 (or null)
    uint2* __restrict__ cvtDst,         // fused16 item rows as 4-half units
    size_t nCvt,
    float4* __restrict__ zA, size_t nzA,
    float4* __restrict__ zB, size_t nzB)
{
    if (blockIdx.x >= GATE_B) {
        size_t stride = (size_t)GATE_X * 256;
        float4 zf = make_float4(0.f, 0.f, 0.f, 0.f);
        size_t tot = nCvt + nzA + nzB;
        for (size_t i = (size_t)(blockIdx.x - GATE_B) * 256 + threadIdx.x; i < tot; i += stride) {
            if (i < nCvt) {
                float4 v = __ldg(cvtSrc + i);
                __half2 a = __floats2half2_rn(v.x, v.y);
                __half2 c = __floats2half2_rn(v.z, v.w);
                uint2 st;
                st.x = *reinterpret_cast<unsigned*>(&a);
                st.y = *reinterpret_cast<unsigned*>(&c);
                cvtDst[i] = st;
            } else if (i < nCvt + nzA) {
                zA[i - nCvt] = zf;
            } else {
                zB[i - nCvt - nzA] = zf;
            }
        }
        return;
    }
    int w = (blockIdx.x * blockDim.x + threadIdx.x) >> 5;
    int lane = threadIdx.x & 31;
    size_t base = (size_t)w * LATDIM + lane * 2;
    float2 z = *reinterpret_cast<const float2*>(Z + base);
    float2 h = *reinterpret_cast<const float2*>(F + base);
    int d = lane * 2;
    float a0 = z.x * __ldg(Wg + d)       + z.y * __ldg(Wg + d + 1)
             + h.x * __ldg(Wg + 64 + d)  + h.y * __ldg(Wg + 64 + d + 1);
    float a1 = z.x * __ldg(Wg + 128 + d) + z.y * __ldg(Wg + 128 + d + 1)
             + h.x * __ldg(Wg + 192 + d) + h.y * __ldg(Wg + 192 + d + 1);
    #pragma unroll
    for (int o = 16; o; o >>= 1) {
        a0 += __shfl_xor_sync(0xffffffffu, a0, o);
        a1 += __shfl_xor_sync(0xffffffffu, a1, o);
    }
    a0 += __ldg(bg);
    a1 += __ldg(bg + 1);
    a0 = a0 > 0.f ? a0 : 0.01f * a0;
    a1 = a1 > 0.f ? a1 : 0.01f * a1;
    float mx = fmaxf(a0, a1);
    float e0 = __expf(a0 - mx), e1 = __expf(a1 - mx);
    float inv = 1.f / (e0 + e1);
    float m0 = e0 * inv, m1 = e1 * inv;
    float2 o2;
    o2.x = z.x * m0 + h.x * m1;
    o2.y = z.y * m0 + h.y * m1;
    *reinterpret_cast<float2*>(F + base) = o2;
    if (F16) {
        *reinterpret_cast<__half2*>(Z16 + base) = __floats2half2_rn(z.x, z.y);
        *reinterpret_cast<__half2*>(F16 + base) = __floats2half2_rn(o2.x, o2.y);
    }
}

// ---------------------------------------------------------------------------
// Final combine: one warp per node; fused[0] rows come straight from uE/iE.
// ---------------------------------------------------------------------------
__global__ __launch_bounds__(256) void final_kernel(
    const float* __restrict__ uE, const float* __restrict__ iE,
    const float* __restrict__ F1, const float* __restrict__ F2,
    const float* __restrict__ F3, const float* __restrict__ F4,
    const float* __restrict__ WL1, const float* __restrict__ bL1,
    const float* __restrict__ WL2, const float* __restrict__ bL2,
    float* __restrict__ out)
{
    int w = (blockIdx.x * blockDim.x + threadIdx.x) >> 5;
    int lane = threadIdx.x & 31;
    if (w >= N_NODE) return;
    bool isU = (w < N_USER);
    const float* W = isU ? WL1 : WL2;
    const float* b = isU ? bL1 : bL2;
    size_t base = (size_t)w * LATDIM + lane * 2;
    float2 f[5];
    f[0] = isU ? *reinterpret_cast<const float2*>(uE + base)
               : *reinterpret_cast<const float2*>(iE + (base - NUF));
    f[1] = *reinterpret_cast<const float2*>(F1 + base);
    f[2] = *reinterpret_cast<const float2*>(F2 + base);
    f[3] = *reinterpret_cast<const float2*>(F3 + base);
    f[4] = *reinterpret_cast<const float2*>(F4 + base);
    float lg[5];
    int d = lane * 2;
    #pragma unroll
    for (int j = 0; j < 5; j++) {
        float acc = 0.f;
        #pragma unroll
        for (int k = 0; k < 5; k++) {
            const float* wr = W + j * 320 + k * 64 + d;
            acc += f[k].x * __ldg(wr) + f[k].y * __ldg(wr + 1);
        }
        lg[j] = acc;
    }
    #pragma unroll
    for (int o = 16; o; o >>= 1) {
        #pragma unroll
        for (int j = 0; j < 5; j++) lg[j] += __shfl_xor_sync(0xffffffffu, lg[j], o);
    }
    float mx = -1e30f;
    #pragma unroll
    for (int j = 0; j < 5; j++) {
        lg[j] += __ldg(b + j);
        lg[j] = lg[j] > 0.f ? lg[j] : 0.01f * lg[j];
        mx = fmaxf(mx, lg[j]);
    }
    float s = 0.f;
    #pragma unroll
    for (int j = 0; j < 5; j++) { lg[j] = __expf(lg[j] - mx); s += lg[j]; }
    float inv = 1.f / s;
    float2 o2 = make_float2(0.f, 0.f);
    #pragma unroll
    for (int j = 0; j < 5; j++) {
        float wk = lg[j] * inv;
        o2.x += wk * f[j].x;
        o2.y += wk * f[j].y;
    }
    *reinterpret_cast<float2*>(out + base) = o2;
}

// ---------------------------------------------------------------------------
// host
// ---------------------------------------------------------------------------
static inline int cdiv_ll(long long a, int b) { return (int)((a + b - 1) / b); }

extern "C" void kernel_launch(void* const* d_in, const int* in_sizes, int n_in,
                              void* d_out, int out_size)
{
    const float* uE  = (const float*)d_in[0];
    const float* iE  = (const float*)d_in[1];
    const float* Wg  = (const float*)d_in[2];   // (5,2,128)
    const float* bg  = (const float*)d_in[3];   // (5,2)
    const float* WL1 = (const float*)d_in[4];   // (5,320)
    const float* bL1 = (const float*)d_in[5];
    const float* WL2 = (const float*)d_in[6];
    const float* bL2 = (const float*)d_in[7];
    const int*   ir  = (const int*)d_in[8];
    const int*   ic  = (const int*)d_in[9];
    const float* iv  = (const float*)d_in[10];
    const int*   sr  = (const int*)d_in[11];
    const int*   sc  = (const int*)d_in[12];
    const float* sv  = (const float*)d_in[13];
    float* out = (float*)d_out;

    void *ps, *pf, *pf16, *ps16, *pe;
    cudaGetSymbolAddress(&ps, g_soc);
    cudaGetSymbolAddress(&pf, g_fused);
    cudaGetSymbolAddress(&pf16, g_fused16);
    cudaGetSymbolAddress(&ps16, g_soc16);
    cudaGetSymbolAddress(&pe, g_epack);

    float* soc[5];
    soc[0] = const_cast<float*>(uE);
    for (int l = 0; l < 4; l++) soc[l + 1] = (float*)ps + (size_t)l * NUF;
    float* fused[5];
    fused[0] = nullptr;  // == concat(uE, iE), consumed via uE/iE + fused16[0]
    for (int k = 1; k <= 4; k++) fused[k] = (float*)pf + (size_t)(k - 1) * NNF;
    __half* fused16[4];
    for (int k = 0; k < 4; k++) fused16[k] = (__half*)pf16 + (size_t)k * NNF;
    // soc gather sources per layer k: k=0 aliases fused16[0] user rows.
    __half* socsrc16[4];
    socsrc16[0] = fused16[0];
    for (int l = 1; l < 4; l++) socsrc16[l] = (__half*)ps16 + (size_t)(l - 1) * NUF;
    unsigned long long* eI = (unsigned long long*)pe;
    unsigned long long* eS = eI + E_INTER;

    // Preamble: pack edges, build fused16[0], zero layer-1 accumulators.
    preamble_kernel<<<PB_I + PB_S + PB_H + PB_Z, 256>>>(
        eI, ir, ic, iv, eS, sr, sc, sv,
        (const float4*)uE, (const float4*)iE, (uint2*)fused16[0],
        (float4*)fused[1], NNF / 4, (float4*)soc[1], NUF / 4);

    const int blocksA = cdiv_ll((long long)(E_INTER / 4) * 16, 256);  // 62500
    const int blocksB = cdiv_ll((long long)(E_SOC / 4) * 16, 256);    // 31250
    const size_t nCvt = (size_t)N_ITEM * LATDIM / 4;                  // 3.2M

    for (int k = 0; k < N_LAYER; k++) {
        spmm_dual_kernel<<<blocksA + blocksB, 256>>>(
            eI, fused16[k], fused[k + 1], E_INTER,
            eS, socsrc16[k], soc[k + 1], E_SOC,
            blocksA);
        bool more = (k <= 2);   // another SpMM layer follows gate k+1
        gate_kernel<<<GATE_B + GATE_X, 256>>>(
            soc[k + 1], fused[k + 1],
            Wg + (size_t)(k + 1) * 256, bg + (size_t)(k + 1) * 2,
            more ? socsrc16[k + 1] : (__half*)nullptr,
            more ? fused16[k + 1] : (__half*)nullptr,
            more ? (const float4*)(fused[k + 1] + NUF) : (const float4*)nullptr,
            more ? (uint2*)(fused16[k + 1] + NUF) : (uint2*)nullptr,
            more ? nCvt : 0,
            more ? (float4*)fused[k + 2] : (float4*)nullptr, more ? NNF / 4 : 0,
            more ? (float4*)soc[k + 2]   : (float4*)nullptr, more ? NUF / 4 : 0);
    }

    final_kernel<<<cdiv_ll((long long)N_NODE * 32, 256), 256>>>(
        uE, iE, fused[1], fused[2], fused[3], fused[4],
        WL1, bL1, WL2, bL2, out);
}

// round 8
// speedup vs baseline: 2.3627x; 1.6367x over previous
#include <cuda_runtime.h>
#include <cuda_fp16.h>
#include <cstdint>

#define N_USER 100000
#define N_ITEM 200000
#define N_NODE 300000
#define LATDIM 64
#define E_INTER 4000000
#define E_SOC   2000000
#define N_LAYER 4

#define NUF ((size_t)N_USER * LATDIM)   // 6.4M elems
#define NNF ((size_t)N_NODE * LATDIM)   // 19.2M elems

// fp16 everywhere: fused16[0] = fp16(concat(uE,iE)); fused16[1..4] and
// soc16[1..4] are fp16 ATOMIC accumulators that double as gather sources,
// gate operands, and final-combine inputs.
__device__ __half g_fused16[5][NNF];
__device__ __half g_soc16[4][NUF];
// packed edges: col(19b) | row(19b)<<19 | fp16(val)<<48, 8 B each.
__device__ __align__(16) unsigned long long g_epack[E_INTER + E_SOC];

// ---------------------------------------------------------------------------
// Preamble: pack both edge lists, build fused16[0], zero layer-1 accumulators.
// ---------------------------------------------------------------------------
#define PB_I 15625           // E_INTER / 256
#define PB_S 7813            // ceil(E_SOC / 256)
#define PB_H 1024            // fp16 build of fused16[0]
#define PB_Z 512             // zero fused16[1], soc16[1]

__device__ __forceinline__ unsigned long long pack_edge(int col, int row, float v) {
    unsigned short hb = __half_as_ushort(__float2half_rn(v));
    return (unsigned long long)(unsigned)col
         | ((unsigned long long)(unsigned)row << 19)
         | ((unsigned long long)hb << 48);
}

__global__ __launch_bounds__(256) void preamble_kernel(
    unsigned long long* __restrict__ eI, const int* __restrict__ ir,
    const int* __restrict__ ic, const float* __restrict__ iv,
    unsigned long long* __restrict__ eS, const int* __restrict__ sr,
    const int* __restrict__ sc, const float* __restrict__ sv,
    const float4* __restrict__ uE4, const float4* __restrict__ iE4,
    uint2* __restrict__ h0,               // fused16[0] as 4-half units
    uint4* __restrict__ zA, size_t nzA,   // fused16[1] as 8-half units
    uint4* __restrict__ zB, size_t nzB)   // soc16[1]
{
    unsigned b = blockIdx.x;
    int tid = threadIdx.x;
    if (b < PB_I) {
        int e = (int)b * 256 + tid;
        eI[e] = pack_edge(__ldg(ic + e), __ldg(ir + e), __ldg(iv + e));
    } else if (b < PB_I + PB_S) {
        int e = (int)(b - PB_I) * 256 + tid;
        if (e < E_SOC)
            eS[e] = pack_edge(__ldg(sc + e), __ldg(sr + e), __ldg(sv + e));
    } else if (b < PB_I + PB_S + PB_H) {
        const size_t nU4 = NUF / 4, nN4 = NNF / 4;
        size_t stride = (size_t)PB_H * 256;
        for (size_t i = (size_t)(b - PB_I - PB_S) * 256 + tid; i < nN4; i += stride) {
            float4 v = (i < nU4) ? __ldg(uE4 + i) : __ldg(iE4 + (i - nU4));
            __half2 a = __floats2half2_rn(v.x, v.y);
            __half2 c = __floats2half2_rn(v.z, v.w);
            uint2 st;
            st.x = *reinterpret_cast<unsigned*>(&a);
            st.y = *reinterpret_cast<unsigned*>(&c);
            h0[i] = st;
        }
    } else {
        size_t stride = (size_t)PB_Z * 256;
        uint4 z = make_uint4(0u, 0u, 0u, 0u);
        size_t tot = nzA + nzB;
        for (size_t i = (size_t)(b - PB_I - PB_S - PB_H) * 256 + tid; i < tot; i += stride) {
            if (i < nzA) zA[i] = z; else zB[i - nzA] = z;
        }
    }
}

// ---------------------------------------------------------------------------
// Dual SpMM, fp16 gather + fp16x2 RED scatter, 4 edges per thread.
// 16 lanes per group (lane owns 4 halves = 8 B of the 128 B row). One
// LDG.128 fetches 2 packed edge records; group g handles records
// {2g,2g+1} and {2(g+nQ),2(g+nQ)+1}.
// Per-edge wavefronts: 1 gather + 1 scatter (vs 1+2 with f32 scatter).
// ---------------------------------------------------------------------------
__device__ __forceinline__ void unpack_edge(unsigned lo, unsigned hi,
                                            int& col, int& row, __half2& val2) {
    col = (int)(lo & 0x7FFFFu);
    row = (int)(((lo >> 19) | (hi << 13)) & 0x7FFFFu);
    __half v = __ushort_as_half((unsigned short)(hi >> 16));
    val2 = __half2half2(v);
}

__device__ __forceinline__ void red_h4(__half* dst, __half2 v2, uint2 x) {
    __half2 a = __hmul2(v2, *reinterpret_cast<__half2*>(&x.x));
    __half2 b = __hmul2(v2, *reinterpret_cast<__half2*>(&x.y));
    asm volatile("red.global.add.noftz.v2.f16x2 [%0], {%1,%2};"
                 :: "l"(dst),
                    "r"(*reinterpret_cast<unsigned*>(&a)),
                    "r"(*reinterpret_cast<unsigned*>(&b))
                 : "memory");
}

__global__ __launch_bounds__(256) void spmm_dual_kernel(
    const unsigned long long* __restrict__ eA, const __half* __restrict__ xA,
    __half* __restrict__ oA, int nA,
    const unsigned long long* __restrict__ eB, const __half* __restrict__ xB,
    __half* __restrict__ oB, int nB,
    int blocksA)
{
    const unsigned long long* E; const __half* X; __half* O; int n; unsigned b;
    if (blockIdx.x < (unsigned)blocksA) { E = eA; X = xA; O = oA; n = nA; b = blockIdx.x; }
    else                                { E = eB; X = xB; O = oB; n = nB; b = blockIdx.x - blocksA; }

    int t = (int)b * 256 + (int)threadIdx.x;
    int lane = t & 15;
    int g = t >> 4;
    int nQ = n >> 2;
    if (g >= nQ) return;

    const uint4* P = reinterpret_cast<const uint4*>(E);
    uint4 q0 = __ldg(P + g);         // records 2g, 2g+1
    uint4 q1 = __ldg(P + g + nQ);    // records 2(g+nQ), 2(g+nQ)+1

    int c0, r0, c1, r1, c2, r2, c3, r3;
    __half2 v0, v1, v2, v3;
    unpack_edge(q0.x, q0.y, c0, r0, v0);
    unpack_edge(q0.z, q0.w, c1, r1, v1);
    unpack_edge(q1.x, q1.y, c2, r2, v2);
    unpack_edge(q1.z, q1.w, c3, r3, v3);

    uint2 x0 = __ldg(reinterpret_cast<const uint2*>(X + (size_t)c0 * LATDIM) + lane);
    uint2 x1 = __ldg(reinterpret_cast<const uint2*>(X + (size_t)c1 * LATDIM) + lane);
    uint2 x2 = __ldg(reinterpret_cast<const uint2*>(X + (size_t)c2 * LATDIM) + lane);
    uint2 x3 = __ldg(reinterpret_cast<const uint2*>(X + (size_t)c3 * LATDIM) + lane);

    red_h4(O + (size_t)r0 * LATDIM + lane * 4, v0, x0);
    red_h4(O + (size_t)r1 * LATDIM + lane * 4, v1, x1);
    red_h4(O + (size_t)r2 * LATDIM + lane * 4, v2, x2);
    red_h4(O + (size_t)r3 * LATDIM + lane * 4, v3, x3);
}

// ---------------------------------------------------------------------------
// Gate: blocks [0,GATE_B): one warp per user row, fp16 in/out (math in f32).
// Blocks [GATE_B,..): zero the next layer's fp16 accumulators.
// ---------------------------------------------------------------------------
#define GATE_B 12500         // N_USER * 32 / 256
#define GATE_X 1024

__global__ __launch_bounds__(256) void gate_kernel(
    const __half* __restrict__ Z,   // soc16[k] [N_USER,64]
    __half* __restrict__ F,         // fused16[k], user rows in/out
    const float* __restrict__ Wg, const float* __restrict__ bg,
    uint4* __restrict__ zA, size_t nzA,
    uint4* __restrict__ zB, size_t nzB)
{
    if (blockIdx.x >= GATE_B) {
        size_t stride = (size_t)GATE_X * 256;
        uint4 zf = make_uint4(0u, 0u, 0u, 0u);
        size_t tot = nzA + nzB;
        for (size_t i = (size_t)(blockIdx.x - GATE_B) * 256 + threadIdx.x; i < tot; i += stride) {
            if (i < nzA) zA[i] = zf; else zB[i - nzA] = zf;
        }
        return;
    }
    int w = (blockIdx.x * blockDim.x + threadIdx.x) >> 5;
    int lane = threadIdx.x & 31;
    size_t base = (size_t)w * LATDIM + lane * 2;
    float2 z = __half22float2(*reinterpret_cast<const __half2*>(Z + base));
    float2 h = __half22float2(*reinterpret_cast<const __half2*>(F + base));
    int d = lane * 2;
    float a0 = z.x * __ldg(Wg + d)       + z.y * __ldg(Wg + d + 1)
             + h.x * __ldg(Wg + 64 + d)  + h.y * __ldg(Wg + 64 + d + 1);
    float a1 = z.x * __ldg(Wg + 128 + d) + z.y * __ldg(Wg + 128 + d + 1)
             + h.x * __ldg(Wg + 192 + d) + h.y * __ldg(Wg + 192 + d + 1);
    #pragma unroll
    for (int o = 16; o; o >>= 1) {
        a0 += __shfl_xor_sync(0xffffffffu, a0, o);
        a1 += __shfl_xor_sync(0xffffffffu, a1, o);
    }
    a0 += __ldg(bg);
    a1 += __ldg(bg + 1);
    a0 = a0 > 0.f ? a0 : 0.01f * a0;
    a1 = a1 > 0.f ? a1 : 0.01f * a1;
    float mx = fmaxf(a0, a1);
    float e0 = __expf(a0 - mx), e1 = __expf(a1 - mx);
    float inv = 1.f / (e0 + e1);
    float m0 = e0 * inv, m1 = e1 * inv;
    *reinterpret_cast<__half2*>(F + base) =
        __floats2half2_rn(z.x * m0 + h.x * m1, z.y * m0 + h.y * m1);
}

// ---------------------------------------------------------------------------
// Final combine: one warp per node; fused[0] rows from uE/iE (f32), deeper
// layers from fp16 accumulators. Math in f32, output f32.
// ---------------------------------------------------------------------------
__global__ __launch_bounds__(256) void final_kernel(
    const float* __restrict__ uE, const float* __restrict__ iE,
    const __half* __restrict__ F1, const __half* __restrict__ F2,
    const __half* __restrict__ F3, const __half* __restrict__ F4,
    const float* __restrict__ WL1, const float* __restrict__ bL1,
    const float* __restrict__ WL2, const float* __restrict__ bL2,
    float* __restrict__ out)
{
    int w = (blockIdx.x * blockDim.x + threadIdx.x) >> 5;
    int lane = threadIdx.x & 31;
    if (w >= N_NODE) return;
    bool isU = (w < N_USER);
    const float* W = isU ? WL1 : WL2;
    const float* b = isU ? bL1 : bL2;
    size_t base = (size_t)w * LATDIM + lane * 2;
    float2 f[5];
    f[0] = isU ? *reinterpret_cast<const float2*>(uE + base)
               : *reinterpret_cast<const float2*>(iE + (base - NUF));
    f[1] = __half22float2(*reinterpret_cast<const __half2*>(F1 + base));
    f[2] = __half22float2(*reinterpret_cast<const __half2*>(F2 + base));
    f[3] = __half22float2(*reinterpret_cast<const __half2*>(F3 + base));
    f[4] = __half22float2(*reinterpret_cast<const __half2*>(F4 + base));
    float lg[5];
    int d = lane * 2;
    #pragma unroll
    for (int j = 0; j < 5; j++) {
        float acc = 0.f;
        #pragma unroll
        for (int k = 0; k < 5; k++) {
            const float* wr = W + j * 320 + k * 64 + d;
            acc += f[k].x * __ldg(wr) + f[k].y * __ldg(wr + 1);
        }
        lg[j] = acc;
    }
    #pragma unroll
    for (int o = 16; o; o >>= 1) {
        #pragma unroll
        for (int j = 0; j < 5; j++) lg[j] += __shfl_xor_sync(0xffffffffu, lg[j], o);
    }
    float mx = -1e30f;
    #pragma unroll
    for (int j = 0; j < 5; j++) {
        lg[j] += __ldg(b + j);
        lg[j] = lg[j] > 0.f ? lg[j] : 0.01f * lg[j];
        mx = fmaxf(mx, lg[j]);
    }
    float s = 0.f;
    #pragma unroll
    for (int j = 0; j < 5; j++) { lg[j] = __expf(lg[j] - mx); s += lg[j]; }
    float inv = 1.f / s;
    float2 o2 = make_float2(0.f, 0.f);
    #pragma unroll
    for (int j = 0; j < 5; j++) {
        float wk = lg[j] * inv;
        o2.x += wk * f[j].x;
        o2.y += wk * f[j].y;
    }
    *reinterpret_cast<float2*>(out + base) = o2;
}

// ---------------------------------------------------------------------------
// host
// ---------------------------------------------------------------------------
static inline int cdiv_ll(long long a, int b) { return (int)((a + b - 1) / b); }

extern "C" void kernel_launch(void* const* d_in, const int* in_sizes, int n_in,
                              void* d_out, int out_size)
{
    const float* uE  = (const float*)d_in[0];
    const float* iE  = (const float*)d_in[1];
    const float* Wg  = (const float*)d_in[2];   // (5,2,128)
    const float* bg  = (const float*)d_in[3];   // (5,2)
    const float* WL1 = (const float*)d_in[4];   // (5,320)
    const float* bL1 = (const float*)d_in[5];
    const float* WL2 = (const float*)d_in[6];
    const float* bL2 = (const float*)d_in[7];
    const int*   ir  = (const int*)d_in[8];
    const int*   ic  = (const int*)d_in[9];
    const float* iv  = (const float*)d_in[10];
    const int*   sr  = (const int*)d_in[11];
    const int*   sc  = (const int*)d_in[12];
    const float* sv  = (const float*)d_in[13];
    float* out = (float*)d_out;

    void *pf16, *ps16, *pe;
    cudaGetSymbolAddress(&pf16, g_fused16);
    cudaGetSymbolAddress(&ps16, g_soc16);
    cudaGetSymbolAddress(&pe, g_epack);

    __half* fused16[5];
    for (int k = 0; k <= 4; k++) fused16[k] = (__half*)pf16 + (size_t)k * NNF;
    __half* soc16[5];
    soc16[0] = nullptr;   // layer-0 soc source = fused16[0] user rows
    for (int l = 1; l <= 4; l++) soc16[l] = (__half*)ps16 + (size_t)(l - 1) * NUF;
    __half* socsrc[4];
    socsrc[0] = fused16[0];
    for (int l = 1; l < 4; l++) socsrc[l] = soc16[l];
    unsigned long long* eI = (unsigned long long*)pe;
    unsigned long long* eS = eI + E_INTER;

    // Preamble: pack edges, build fused16[0], zero layer-1 accumulators.
    preamble_kernel<<<PB_I + PB_S + PB_H + PB_Z, 256>>>(
        eI, ir, ic, iv, eS, sr, sc, sv,
        (const float4*)uE, (const float4*)iE, (uint2*)fused16[0],
        (uint4*)fused16[1], NNF / 8, (uint4*)soc16[1], NUF / 8);

    const int blocksA = cdiv_ll((long long)(E_INTER / 4) * 16, 256);  // 62500
    const int blocksB = cdiv_ll((long long)(E_SOC / 4) * 16, 256);    // 31250

    for (int k = 0; k < N_LAYER; k++) {
        spmm_dual_kernel<<<blocksA + blocksB, 256>>>(
            eI, fused16[k], fused16[k + 1], E_INTER,
            eS, socsrc[k], soc16[k + 1], E_SOC,
            blocksA);
        bool more = (k <= 2);   // another SpMM layer follows gate k+1
        gate_kernel<<<GATE_B + GATE_X, 256>>>(
            soc16[k + 1], fused16[k + 1],
            Wg + (size_t)(k + 1) * 256, bg + (size_t)(k + 1) * 2,
            more ? (uint4*)fused16[k + 2] : (uint4*)nullptr, more ? NNF / 8 : 0,
            more ? (uint4*)soc16[k + 2]   : (uint4*)nullptr, more ? NUF / 8 : 0);
    }

    final_kernel<<<cdiv_ll((long long)N_NODE * 32, 256), 256>>>(
        uE, iE, fused16[1], fused16[2], fused16[3], fused16[4],
        WL1, bL1, WL2, bL2, out);
}